// round 2
// baseline (speedup 1.0000x reference)
#include <cuda_runtime.h>

#define N 4096
#define D 256
#define C 1000
#define BM 64
#define BK 32

// Global scratch (no allocations allowed in kernel_launch).
__device__ double g_acc[4];        // [0]=label sumsq, [1..3]=feature sumsq
__device__ float  g_sqn[6][N];     // row squared norms: 0..2 = pred_f, 3..5 = target_f

// ---------------------------------------------------------------------------
__global__ void zero_kernel() {
    if (threadIdx.x < 4) g_acc[threadIdx.x] = 0.0;
}

// ---------------------------------------------------------------------------
// Row squared norms for all 6 feature matrices. One warp per row.
__global__ void sqn_kernel(const float* __restrict__ f0, const float* __restrict__ f1,
                           const float* __restrict__ f2, const float* __restrict__ f3,
                           const float* __restrict__ f4, const float* __restrict__ f5) {
    int gw   = (blockIdx.x * blockDim.x + threadIdx.x) >> 5;
    int lane = threadIdx.x & 31;
    if (gw >= 6 * N) return;
    int f = gw >> 12;          // /4096
    int row = gw & (N - 1);
    const float* src;
    switch (f) {
        case 0: src = f0; break; case 1: src = f1; break; case 2: src = f2; break;
        case 3: src = f3; break; case 4: src = f4; break; default: src = f5; break;
    }
    const float4* p = (const float4*)(src + (size_t)row * D);
    float s = 0.f;
#pragma unroll
    for (int i = 0; i < 2; i++) {
        float4 v = p[lane + 32 * i];
        s += v.x * v.x + v.y * v.y + v.z * v.z + v.w * v.w;
    }
#pragma unroll
    for (int o = 16; o; o >>= 1) s += __shfl_xor_sync(0xffffffffu, s, o);
    if (lane == 0) g_sqn[f][row] = s;
}

// ---------------------------------------------------------------------------
// Label MSE sum: sum((pred - target)^2) over N*C elements.
__global__ void label_kernel(const float* __restrict__ pred,
                             const float* __restrict__ target) {
    __shared__ float sred[256];
    const int n4 = N * C / 4;
    float s = 0.f;
    for (int i = blockIdx.x * blockDim.x + threadIdx.x; i < n4;
         i += gridDim.x * blockDim.x) {
        float4 a = ((const float4*)pred)[i];
        float4 b = ((const float4*)target)[i];
        float dx = a.x - b.x, dy = a.y - b.y, dz = a.z - b.z, dw = a.w - b.w;
        s += dx * dx + dy * dy + dz * dz + dw * dw;
    }
    sred[threadIdx.x] = s;
    __syncthreads();
    for (int o = 128; o; o >>= 1) {
        if (threadIdx.x < o) sred[threadIdx.x] += sred[threadIdx.x + o];
        __syncthreads();
    }
    if (threadIdx.x == 0) atomicAdd(&g_acc[0], (double)sred[0]);
}

// ---------------------------------------------------------------------------
// Fused pairwise kernel: for one 64x64 tile of the NxN distance matrices,
// compute dotP = Pi·Pj and dotT = Ti·Tj (two SGEMM micro-tiles), then
// d = sqrt(max(sqn_i + sqn_j - 2*dot, 0)) for each, accumulate (dP - dT)^2.
// Only upper-triangular tiles are computed (symmetry), off-diag weighted x2.
__global__ void __launch_bounds__(256)
pair_kernel(const float* __restrict__ pf0, const float* __restrict__ pf1,
            const float* __restrict__ pf2, const float* __restrict__ tf0,
            const float* __restrict__ tf1, const float* __restrict__ tf2) {
    int bj = blockIdx.x, bi = blockIdx.y, f = blockIdx.z;
    if (bj < bi) return;

    const float *P, *T;
    if (f == 0)      { P = pf0; T = tf0; }
    else if (f == 1) { P = pf1; T = tf1; }
    else             { P = pf2; T = tf2; }

    __shared__ float sPi[BM][BK + 1], sPj[BM][BK + 1];
    __shared__ float sTi[BM][BK + 1], sTj[BM][BK + 1];
    __shared__ float sred[256];

    const int tx = threadIdx.x, ty = threadIdx.y;   // 16x16
    const int tid = ty * 16 + tx;
    const int rowI = bi * BM, rowJ = bj * BM;

    float accP[4][4] = {}, accT[4][4] = {};

    for (int k0 = 0; k0 < D; k0 += BK) {
        // Load 4 tiles of 64x32 floats. 512 float4 per tile; 2 per thread.
#pragma unroll
        for (int l = tid; l < (BM * BK / 4); l += 256) {
            int m  = l >> 3;
            int kk = (l & 7) << 2;
            float4 v;
            v = *(const float4*)&P[(size_t)(rowI + m) * D + k0 + kk];
            sPi[m][kk] = v.x; sPi[m][kk + 1] = v.y; sPi[m][kk + 2] = v.z; sPi[m][kk + 3] = v.w;
            v = *(const float4*)&P[(size_t)(rowJ + m) * D + k0 + kk];
            sPj[m][kk] = v.x; sPj[m][kk + 1] = v.y; sPj[m][kk + 2] = v.z; sPj[m][kk + 3] = v.w;
            v = *(const float4*)&T[(size_t)(rowI + m) * D + k0 + kk];
            sTi[m][kk] = v.x; sTi[m][kk + 1] = v.y; sTi[m][kk + 2] = v.z; sTi[m][kk + 3] = v.w;
            v = *(const float4*)&T[(size_t)(rowJ + m) * D + k0 + kk];
            sTj[m][kk] = v.x; sTj[m][kk + 1] = v.y; sTj[m][kk + 2] = v.z; sTj[m][kk + 3] = v.w;
        }
        __syncthreads();

#pragma unroll
        for (int k = 0; k < BK; k++) {
            float aP[4], bP[4], aT[4], bT[4];
#pragma unroll
            for (int r = 0; r < 4; r++) {
                aP[r] = sPi[ty * 4 + r][k];
                aT[r] = sTi[ty * 4 + r][k];
                bP[r] = sPj[tx * 4 + r][k];
                bT[r] = sTj[tx * 4 + r][k];
            }
#pragma unroll
            for (int r = 0; r < 4; r++)
#pragma unroll
                for (int c = 0; c < 4; c++) {
                    accP[r][c] += aP[r] * bP[c];
                    accT[r][c] += aT[r] * bT[c];
                }
        }
        __syncthreads();
    }

    // Epilogue: distances, diff^2, tile reduction.
    const float w = (bi == bj) ? 1.0f : 2.0f;
    float s = 0.f;
#pragma unroll
    for (int r = 0; r < 4; r++) {
        int i = rowI + ty * 4 + r;
        float sqPi = g_sqn[f][i];
        float sqTi = g_sqn[3 + f][i];
#pragma unroll
        for (int c = 0; c < 4; c++) {
            int j = rowJ + tx * 4 + c;
            float sp = sqPi + g_sqn[f][j]     - 2.f * accP[r][c];
            float st = sqTi + g_sqn[3 + f][j] - 2.f * accT[r][c];
            float dp = sp > 0.f ? sqrtf(sp) : 0.f;
            float dt = st > 0.f ? sqrtf(st) : 0.f;
            float d = dp - dt;
            s += d * d;
        }
    }
    sred[tid] = s * w;
    __syncthreads();
    for (int o = 128; o; o >>= 1) {
        if (tid < o) sred[tid] += sred[tid + o];
        __syncthreads();
    }
    if (tid == 0) atomicAdd(&g_acc[1 + f], (double)sred[0]);
}

// ---------------------------------------------------------------------------
__global__ void final_kernel(float* __restrict__ out) {
    double label = g_acc[0] / ((double)N * (double)C);
    double feat  = (g_acc[1] + g_acc[2] + g_acc[3]) / ((double)N * (double)N);
    out[0] = (float)((1.0 - 0.8) * label + 0.8 * feat / 3.0);
}

// ---------------------------------------------------------------------------
extern "C" void kernel_launch(void* const* d_in, const int* in_sizes, int n_in,
                              void* d_out, int out_size) {
    const float* pred   = (const float*)d_in[0];
    const float* target = (const float*)d_in[1];
    const float* pf0 = (const float*)d_in[2];
    const float* pf1 = (const float*)d_in[3];
    const float* pf2 = (const float*)d_in[4];
    const float* tf0 = (const float*)d_in[5];
    const float* tf1 = (const float*)d_in[6];
    const float* tf2 = (const float*)d_in[7];
    float* out = (float*)d_out;

    zero_kernel<<<1, 32>>>();

    // Row squared norms: 6*4096 rows, one warp each, 8 rows per 256-thread block.
    sqn_kernel<<<(6 * N) / 8, 256>>>(pf0, pf1, pf2, tf0, tf1, tf2);

    label_kernel<<<512, 256>>>(pred, target);

    dim3 grid(N / BM, N / BM, 3);   // 64 x 64 x 3; lower-tri blocks exit early
    dim3 block(16, 16);
    pair_kernel<<<grid, block>>>(pf0, pf1, pf2, tf0, tf1, tf2);

    final_kernel<<<1, 1>>>(out);
}